// round 5
// baseline (speedup 1.0000x reference)
#include <cuda_runtime.h>
#include <math.h>

#define NB 2
#define SS 2048
#define NH 16
#define HD 64
#define DD 1024
#define D3 3072
#define MTOT (NB*SS)

// Scratch (allocation-free rule: device globals)
__device__ float g_q[NB*NH*SS*HD];     // [B,H,S,hd]
__device__ float g_k[NB*NH*SS*HD];
__device__ float g_v[NB*NH*SS*HD];
__device__ float g_attn[MTOT*DD];      // merged heads [B*S, D]

__device__ __forceinline__ unsigned f2t(float x) {
    unsigned u;
    asm("cvt.rna.tf32.f32 %0, %1;" : "=r"(u) : "f"(x));
    return u;
}

__device__ __forceinline__ void mma8(float* d, const unsigned* a, const unsigned* b) {
    asm volatile(
        "mma.sync.aligned.m16n8k8.row.col.f32.tf32.tf32.f32 "
        "{%0,%1,%2,%3}, {%4,%5,%6,%7}, {%8,%9}, {%0,%1,%2,%3};\n"
        : "+f"(d[0]), "+f"(d[1]), "+f"(d[2]), "+f"(d[3])
        : "r"(a[0]), "r"(a[1]), "r"(a[2]), "r"(a[3]), "r"(b[0]), "r"(b[1]));
}

// ---------------------------------------------------------------------------
// TF32 GEMM: C[M,N] = A[M,1024] @ W[1024,N] (+bias) (+lora, scatter q/k/v)
// 128x128 block tile, BK=32, 256 threads (8 warps as 4x2), warp tile 32x64.
// Double-buffered smem. As[m][k] stride 36, Bs[k][n] stride 136.
// __launch_bounds__(256,2): cap regs at 128 so 2 CTAs/SM co-reside.
// ---------------------------------------------------------------------------
#define ASTR 36
#define BSTR 136
#define ABUF (128*ASTR)          // 4608 u32
#define BBUF (32*BSTR)           // 4352 u32
#define GBUF (ABUF + BBUF)       // per stage
#define GSMEM (2*GBUF*4)         // bytes = 71680

template<int N, bool QKV>
__global__ __launch_bounds__(256, 2)
void gemm_tf32(const float* __restrict__ Ain, const float* __restrict__ W,
               const float* __restrict__ bias, const float* __restrict__ lora,
               float* __restrict__ C)
{
    extern __shared__ unsigned sg[];
    const float* A = QKV ? Ain : g_attn;
    const int K = DD;

    const int tid  = threadIdx.x;
    const int warp = tid >> 5, lane = tid & 31;
    const int g = lane >> 2, t = lane & 3;
    const int wm = warp & 3, wn = warp >> 2;         // 4 x 2 warps
    const int bm = blockIdx.y * 128, bn = blockIdx.x * 128;

    // global load coords
    const int rowA = tid >> 3, kqA = tid & 7;        // A: 4 rows strided 32
    const int kB = tid >> 3, cqB = tid & 7;          // B: row kB, 4 col-quads

    float acc[2][8][4];
#pragma unroll
    for (int mf = 0; mf < 2; mf++)
#pragma unroll
        for (int nf = 0; nf < 8; nf++)
#pragma unroll
            for (int e = 0; e < 4; e++) acc[mf][nf][e] = 0.f;

    float4 ra[4], rb[4];

    // prologue: tile 0
#pragma unroll
    for (int i = 0; i < 4; i++)
        ra[i] = *(const float4*)(A + (size_t)(bm + rowA + 32 * i) * K + kqA * 4);
#pragma unroll
    for (int i = 0; i < 4; i++)
        rb[i] = *(const float4*)(W + (size_t)kB * N + bn + (cqB + 8 * i) * 4);

    unsigned* As = sg;
    unsigned* Bs = sg + ABUF;
#pragma unroll
    for (int i = 0; i < 4; i++) {
        uint4 u = make_uint4(f2t(ra[i].x), f2t(ra[i].y), f2t(ra[i].z), f2t(ra[i].w));
        *(uint4*)(As + (rowA + 32 * i) * ASTR + kqA * 4) = u;
        uint4 v = make_uint4(f2t(rb[i].x), f2t(rb[i].y), f2t(rb[i].z), f2t(rb[i].w));
        *(uint4*)(Bs + kB * BSTR + (cqB + 8 * i) * 4) = v;
    }
    __syncthreads();

    const int NT = K / 32;   // 32 iterations
    for (int it = 0; it < NT; ++it) {
        if (it < NT - 1) {
            int k0 = (it + 1) * 32;
#pragma unroll
            for (int i = 0; i < 4; i++)
                ra[i] = *(const float4*)(A + (size_t)(bm + rowA + 32 * i) * K + k0 + kqA * 4);
#pragma unroll
            for (int i = 0; i < 4; i++)
                rb[i] = *(const float4*)(W + (size_t)(k0 + kB) * N + bn + (cqB + 8 * i) * 4);
        }

        const unsigned* Ac = sg + (it & 1) * GBUF;
        const unsigned* Bc = Ac + ABUF;
#pragma unroll
        for (int ks = 0; ks < 4; ks++) {
            const int kb = ks * 8;
            unsigned ua[2][4];
#pragma unroll
            for (int mf = 0; mf < 2; mf++) {
                int rbm = wm * 32 + mf * 16;
                ua[mf][0] = Ac[(rbm + g) * ASTR + kb + t];
                ua[mf][1] = Ac[(rbm + g + 8) * ASTR + kb + t];
                ua[mf][2] = Ac[(rbm + g) * ASTR + kb + t + 4];
                ua[mf][3] = Ac[(rbm + g + 8) * ASTR + kb + t + 4];
            }
#pragma unroll
            for (int nf = 0; nf < 8; nf++) {
                unsigned ub[2];
                int col = wn * 64 + nf * 8 + g;
                ub[0] = Bc[(kb + t) * BSTR + col];
                ub[1] = Bc[(kb + t + 4) * BSTR + col];
                mma8(acc[0][nf], ua[0], ub);
                mma8(acc[1][nf], ua[1], ub);
            }
        }

        if (it < NT - 1) {
            unsigned* An = sg + ((it + 1) & 1) * GBUF;
            unsigned* Bn = An + ABUF;
#pragma unroll
            for (int i = 0; i < 4; i++) {
                uint4 u = make_uint4(f2t(ra[i].x), f2t(ra[i].y), f2t(ra[i].z), f2t(ra[i].w));
                *(uint4*)(An + (rowA + 32 * i) * ASTR + kqA * 4) = u;
                uint4 v = make_uint4(f2t(rb[i].x), f2t(rb[i].y), f2t(rb[i].z), f2t(rb[i].w));
                *(uint4*)(Bn + kB * BSTR + (cqB + 8 * i) * 4) = v;
            }
            __syncthreads();
        }
    }

    // epilogue
#pragma unroll
    for (int mf = 0; mf < 2; mf++) {
#pragma unroll
        for (int nf = 0; nf < 8; nf++) {
            int c = bn + wn * 64 + nf * 8 + 2 * t;
            float2 bi = *(const float2*)(bias + c);
#pragma unroll
            for (int half = 0; half < 2; half++) {
                int r = bm + wm * 32 + mf * 16 + g + half * 8;
                float v0 = acc[mf][nf][half * 2 + 0] + bi.x;
                float v1 = acc[mf][nf][half * 2 + 1] + bi.y;
                if (QKV) {
                    float2 lo = *(const float2*)(lora + (size_t)r * D3 + c);
                    v0 += lo.x; v1 += lo.y;
                    int which = c >> 10, rr = c & 1023;
                    int h = rr >> 6, d = rr & 63;
                    int b_ = r >> 11, s = r & 2047;
                    float* dst = (which == 0) ? g_q : (which == 1) ? g_k : g_v;
                    *(float2*)(dst + ((size_t)((b_ * NH + h) * SS + s)) * HD + d) =
                        make_float2(v0, v1);
                } else {
                    *(float2*)(C + (size_t)r * N + c) = make_float2(v0, v1);
                }
            }
        }
    }
}

// ---------------------------------------------------------------------------
// Flash attention, tf32 mma, causal. Block = (bh, 64-row q tile), 4 warps.
// Warp w owns rows w*16..w*16+15 (all 64 key cols / all 64 d cols).
// Smem: Ks[64][68], Vs[64][72], Ps[64][68] (Ps doubles as Q staging).
// __launch_bounds__(128,3): 3 CTAs/SM (12 warps) to hide latency.
// ---------------------------------------------------------------------------
#define KSTR 68
#define VSTR 72
#define PSTR 68
#define FSMEM ((64*KSTR + 64*VSTR + 64*PSTR) * 4)   // 53248 bytes

__global__ __launch_bounds__(128, 3)
void flash_tf32()
{
    extern __shared__ unsigned smf[];
    unsigned* Ks = smf;
    unsigned* Vs = Ks + 64 * KSTR;
    unsigned* Ps = Vs + 64 * VSTR;

    const int qi = (int)gridDim.x - 1 - (int)blockIdx.x;   // heavy blocks first
    const int bh = blockIdx.y;
    const float* Qg = g_q + (size_t)bh * SS * HD;
    const float* Kg = g_k + (size_t)bh * SS * HD;
    const float* Vg = g_v + (size_t)bh * SS * HD;

    const int tid = threadIdx.x;
    const int warp = tid >> 5, lane = tid & 31;
    const int g = lane >> 2, t = lane & 3;
    const int rb = warp * 16;

    // stage Q (raw bits) into Ps area
#pragma unroll
    for (int i = 0; i < 8; i++) {
        int idx = tid + i * 128;
        int r = idx >> 4, d4 = (idx & 15) * 4;
        float4 q4 = *(const float4*)(Qg + (size_t)(qi * 64 + r) * HD + d4);
        *(uint4*)(Ps + r * PSTR + d4) =
            make_uint4(__float_as_uint(q4.x), __float_as_uint(q4.y),
                       __float_as_uint(q4.z), __float_as_uint(q4.w));
    }
    __syncthreads();

    // build Q fragments (scaled by 1/8, tf32)
    unsigned qa[8][4];
#pragma unroll
    for (int j8 = 0; j8 < 8; j8++) {
        qa[j8][0] = f2t(__uint_as_float(Ps[(rb + g) * PSTR + j8 * 8 + t]) * 0.125f);
        qa[j8][1] = f2t(__uint_as_float(Ps[(rb + g + 8) * PSTR + j8 * 8 + t]) * 0.125f);
        qa[j8][2] = f2t(__uint_as_float(Ps[(rb + g) * PSTR + j8 * 8 + t + 4]) * 0.125f);
        qa[j8][3] = f2t(__uint_as_float(Ps[(rb + g + 8) * PSTR + j8 * 8 + t + 4]) * 0.125f);
    }

    float o[8][4];
#pragma unroll
    for (int nf = 0; nf < 8; nf++)
#pragma unroll
        for (int e = 0; e < 4; e++) o[nf][e] = 0.f;
    float ml = -1e30f, mh = -1e30f, ll = 0.f, lh = 0.f;

    for (int j = 0; j <= qi; j++) {
        __syncthreads();   // prior iter done with Ks/Vs (and Q staging on iter 0)
        // load K,V tile (tf32-converted)
#pragma unroll
        for (int i = 0; i < 8; i++) {
            int idx = tid + i * 128;
            int r = idx >> 4, d4 = (idx & 15) * 4;
            float4 k4 = *(const float4*)(Kg + (size_t)(j * 64 + r) * HD + d4);
            *(uint4*)(Ks + r * KSTR + d4) =
                make_uint4(f2t(k4.x), f2t(k4.y), f2t(k4.z), f2t(k4.w));
            float4 v4 = *(const float4*)(Vg + (size_t)(j * 64 + r) * HD + d4);
            *(uint4*)(Vs + r * VSTR + d4) =
                make_uint4(f2t(v4.x), f2t(v4.y), f2t(v4.z), f2t(v4.w));
        }
        __syncthreads();

        // S = Q K^T  (rows rb..rb+15 x 64 keys)
        float s[8][4];
#pragma unroll
        for (int nf = 0; nf < 8; nf++) {
#pragma unroll
            for (int e = 0; e < 4; e++) s[nf][e] = 0.f;
#pragma unroll
            for (int j8 = 0; j8 < 8; j8++) {
                unsigned kb[2];
                kb[0] = Ks[(nf * 8 + g) * KSTR + j8 * 8 + t];
                kb[1] = Ks[(nf * 8 + g) * KSTR + j8 * 8 + t + 4];
                mma8(s[nf], qa[j8], kb);
            }
        }

        // causal mask on diagonal tile
        if (j == qi) {
#pragma unroll
            for (int nf = 0; nf < 8; nf++) {
                int c0 = nf * 8 + 2 * t, c1 = c0 + 1;
                int rlo = rb + g, rhi = rlo + 8;
                if (c0 > rlo) s[nf][0] = -1e30f;
                if (c1 > rlo) s[nf][1] = -1e30f;
                if (c0 > rhi) s[nf][2] = -1e30f;
                if (c1 > rhi) s[nf][3] = -1e30f;
            }
        }

        // online softmax (rows rlo = rb+g, rhi = rb+g+8)
        float mxl = -1e30f, mxh = -1e30f;
#pragma unroll
        for (int nf = 0; nf < 8; nf++) {
            mxl = fmaxf(mxl, fmaxf(s[nf][0], s[nf][1]));
            mxh = fmaxf(mxh, fmaxf(s[nf][2], s[nf][3]));
        }
        mxl = fmaxf(mxl, __shfl_xor_sync(0xffffffffu, mxl, 1));
        mxl = fmaxf(mxl, __shfl_xor_sync(0xffffffffu, mxl, 2));
        mxh = fmaxf(mxh, __shfl_xor_sync(0xffffffffu, mxh, 1));
        mxh = fmaxf(mxh, __shfl_xor_sync(0xffffffffu, mxh, 2));
        float nml = fmaxf(ml, mxl), nmh = fmaxf(mh, mxh);
        float cl = __expf(ml - nml), ch = __expf(mh - nmh);
        float suml = 0.f, sumh = 0.f;
#pragma unroll
        for (int nf = 0; nf < 8; nf++) {
            s[nf][0] = __expf(s[nf][0] - nml);
            s[nf][1] = __expf(s[nf][1] - nml);
            s[nf][2] = __expf(s[nf][2] - nmh);
            s[nf][3] = __expf(s[nf][3] - nmh);
            suml += s[nf][0] + s[nf][1];
            sumh += s[nf][2] + s[nf][3];
        }
        suml += __shfl_xor_sync(0xffffffffu, suml, 1);
        suml += __shfl_xor_sync(0xffffffffu, suml, 2);
        sumh += __shfl_xor_sync(0xffffffffu, sumh, 1);
        sumh += __shfl_xor_sync(0xffffffffu, sumh, 2);
        ll = ll * cl + suml; lh = lh * ch + sumh;
        ml = nml; mh = nmh;
#pragma unroll
        for (int nf = 0; nf < 8; nf++) {
            o[nf][0] *= cl; o[nf][1] *= cl;
            o[nf][2] *= ch; o[nf][3] *= ch;
        }

        // write P (tf32) to per-warp rows of Ps
#pragma unroll
        for (int nf = 0; nf < 8; nf++) {
            Ps[(rb + g) * PSTR + nf * 8 + 2 * t]     = f2t(s[nf][0]);
            Ps[(rb + g) * PSTR + nf * 8 + 2 * t + 1] = f2t(s[nf][1]);
            Ps[(rb + g + 8) * PSTR + nf * 8 + 2 * t]     = f2t(s[nf][2]);
            Ps[(rb + g + 8) * PSTR + nf * 8 + 2 * t + 1] = f2t(s[nf][3]);
        }
        __syncwarp();

        // O += P V
        unsigned pa[8][4];
#pragma unroll
        for (int j8 = 0; j8 < 8; j8++) {
            pa[j8][0] = Ps[(rb + g) * PSTR + j8 * 8 + t];
            pa[j8][1] = Ps[(rb + g + 8) * PSTR + j8 * 8 + t];
            pa[j8][2] = Ps[(rb + g) * PSTR + j8 * 8 + t + 4];
            pa[j8][3] = Ps[(rb + g + 8) * PSTR + j8 * 8 + t + 4];
        }
#pragma unroll
        for (int nf = 0; nf < 8; nf++) {
#pragma unroll
            for (int j8 = 0; j8 < 8; j8++) {
                unsigned vb[2];
                vb[0] = Vs[(j8 * 8 + t) * VSTR + nf * 8 + g];
                vb[1] = Vs[(j8 * 8 + t + 4) * VSTR + nf * 8 + g];
                mma8(o[nf], pa[j8], vb);
            }
        }
    }

    // normalize + store merged heads
    const int b_ = bh >> 4, h = bh & 15;
    float rl = 1.f / ll, rh = 1.f / lh;
    int rlo = qi * 64 + rb + g, rhi = rlo + 8;
#pragma unroll
    for (int nf = 0; nf < 8; nf++) {
        int d = nf * 8 + 2 * t;
        *(float2*)(g_attn + (size_t)(b_ * SS + rlo) * DD + h * HD + d) =
            make_float2(o[nf][0] * rl, o[nf][1] * rl);
        *(float2*)(g_attn + (size_t)(b_ * SS + rhi) * DD + h * HD + d) =
            make_float2(o[nf][2] * rh, o[nf][3] * rh);
    }
}

// ---------------------------------------------------------------------------
extern "C" void kernel_launch(void* const* d_in, const int* in_sizes, int n_in,
                              void* d_out, int out_size)
{
    const float* hs     = (const float*)d_in[0];
    const float* lora   = (const float*)d_in[1];
    const float* w_attn = (const float*)d_in[2];
    const float* b_attn = (const float*)d_in[3];
    const float* w_proj = (const float*)d_in[4];
    const float* b_proj = (const float*)d_in[5];
    float* out = (float*)d_out;

    cudaFuncSetAttribute(gemm_tf32<D3, true>,
                         cudaFuncAttributeMaxDynamicSharedMemorySize, GSMEM);
    cudaFuncSetAttribute(gemm_tf32<DD, false>,
                         cudaFuncAttributeMaxDynamicSharedMemorySize, GSMEM);
    cudaFuncSetAttribute(flash_tf32,
                         cudaFuncAttributeMaxDynamicSharedMemorySize, FSMEM);

    gemm_tf32<D3, true><<<dim3(D3 / 128, MTOT / 128), 256, GSMEM>>>(
        hs, w_attn, b_attn, lora, nullptr);
    flash_tf32<<<dim3(SS / 64, NB * NH), 128, FSMEM>>>();
    gemm_tf32<DD, false><<<dim3(DD / 128, MTOT / 128), 256, GSMEM>>>(
        nullptr, w_proj, b_proj, nullptr, out);
}

// round 6
// speedup vs baseline: 1.0354x; 1.0354x over previous
#include <cuda_runtime.h>
#include <math.h>

#define NB 2
#define SS 2048
#define NH 16
#define HD 64
#define DD 1024
#define D3 3072
#define MTOT (NB*SS)

// Scratch (allocation-free rule: device globals)
__device__ float g_q[NB*NH*SS*HD];     // [B,H,S,hd]
__device__ float g_k[NB*NH*SS*HD];
__device__ float g_v[NB*NH*SS*HD];
__device__ float g_attn[MTOT*DD];      // merged heads [B*S, D]

__device__ __forceinline__ unsigned f2t(float x) {
    unsigned u;
    asm("cvt.rna.tf32.f32 %0, %1;" : "=r"(u) : "f"(x));
    return u;
}

__device__ __forceinline__ void mma8(float* d, const unsigned* a, const unsigned* b) {
    asm volatile(
        "mma.sync.aligned.m16n8k8.row.col.f32.tf32.tf32.f32 "
        "{%0,%1,%2,%3}, {%4,%5,%6,%7}, {%8,%9}, {%0,%1,%2,%3};\n"
        : "+f"(d[0]), "+f"(d[1]), "+f"(d[2]), "+f"(d[3])
        : "r"(a[0]), "r"(a[1]), "r"(a[2]), "r"(a[3]), "r"(b[0]), "r"(b[1]));
}

// ---------------------------------------------------------------------------
// TF32 GEMM: C[M,N] = A[M,1024] @ W[1024,N] (+bias) (+lora, scatter q/k/v)
// 128x128 CTA tile, BK=32, 128 threads (4 warps as 2x2), warp tile 64x64.
// Fragment traffic: 1.0 LDS-word per MMA (vs 1.5 with 32x64 warp tiles).
// Double-buffered smem. As[m][k] stride 36, Bs[k][n] stride 136.
// __launch_bounds__(128,2): 2 CTAs/SM, reg budget 256/thread.
// ---------------------------------------------------------------------------
#define ASTR 36
#define BSTR 136
#define ABUF (128*ASTR)          // 4608 u32
#define BBUF (32*BSTR)           // 4352 u32
#define GBUF (ABUF + BBUF)       // per stage
#define GSMEM (2*GBUF*4)         // bytes = 71680

template<int N, bool QKV>
__global__ __launch_bounds__(128, 2)
void gemm_tf32(const float* __restrict__ Ain, const float* __restrict__ W,
               const float* __restrict__ bias, const float* __restrict__ lora,
               float* __restrict__ C)
{
    extern __shared__ unsigned sg[];
    const float* A = QKV ? Ain : g_attn;
    const int K = DD;

    const int tid  = threadIdx.x;
    const int warp = tid >> 5, lane = tid & 31;
    const int g = lane >> 2, t = lane & 3;
    const int wm = warp & 1, wn = warp >> 1;         // 2 x 2 warps
    const int bm = blockIdx.y * 128, bn = blockIdx.x * 128;

    // global/staging coords (8 float4 per thread per array)
    const int rowA = tid >> 3, quadA = tid & 7;      // A: rows rowA+16i, quad quadA
    const int kB = tid >> 3, qB = tid & 7;           // B: k rows kB+16(i>>2), quads qB+8(i&3)

    float acc[4][8][4];
#pragma unroll
    for (int mf = 0; mf < 4; mf++)
#pragma unroll
        for (int nf = 0; nf < 8; nf++)
#pragma unroll
            for (int e = 0; e < 4; e++) acc[mf][nf][e] = 0.f;

    float4 ra[8], rb[8];

    // prologue: tile 0
#pragma unroll
    for (int i = 0; i < 8; i++)
        ra[i] = *(const float4*)(A + (size_t)(bm + rowA + 16 * i) * K + quadA * 4);
#pragma unroll
    for (int i = 0; i < 8; i++)
        rb[i] = *(const float4*)(W + (size_t)(kB + 16 * (i >> 2)) * N + bn +
                                 (qB + 8 * (i & 3)) * 4);

    {
        unsigned* As = sg;
        unsigned* Bs = sg + ABUF;
#pragma unroll
        for (int i = 0; i < 8; i++) {
            *(uint4*)(As + (rowA + 16 * i) * ASTR + quadA * 4) =
                make_uint4(f2t(ra[i].x), f2t(ra[i].y), f2t(ra[i].z), f2t(ra[i].w));
            *(uint4*)(Bs + (kB + 16 * (i >> 2)) * BSTR + (qB + 8 * (i & 3)) * 4) =
                make_uint4(f2t(rb[i].x), f2t(rb[i].y), f2t(rb[i].z), f2t(rb[i].w));
        }
    }
    __syncthreads();

    const int NT = K / 32;   // 32 iterations
    for (int it = 0; it < NT; ++it) {
        if (it < NT - 1) {
            int k0 = (it + 1) * 32;
#pragma unroll
            for (int i = 0; i < 8; i++)
                ra[i] = *(const float4*)(A + (size_t)(bm + rowA + 16 * i) * K + k0 + quadA * 4);
#pragma unroll
            for (int i = 0; i < 8; i++)
                rb[i] = *(const float4*)(W + (size_t)(k0 + kB + 16 * (i >> 2)) * N + bn +
                                         (qB + 8 * (i & 3)) * 4);
        }

        const unsigned* Ac = sg + (it & 1) * GBUF;
        const unsigned* Bc = Ac + ABUF;
#pragma unroll
        for (int ks = 0; ks < 4; ks++) {
            const int kb = ks * 8;
            unsigned ua[4][4];
#pragma unroll
            for (int mf = 0; mf < 4; mf++) {
                int rbm = wm * 64 + mf * 16;
                ua[mf][0] = Ac[(rbm + g) * ASTR + kb + t];
                ua[mf][1] = Ac[(rbm + g + 8) * ASTR + kb + t];
                ua[mf][2] = Ac[(rbm + g) * ASTR + kb + t + 4];
                ua[mf][3] = Ac[(rbm + g + 8) * ASTR + kb + t + 4];
            }
#pragma unroll
            for (int nf = 0; nf < 8; nf++) {
                unsigned ub[2];
                int col = wn * 64 + nf * 8 + g;
                ub[0] = Bc[(kb + t) * BSTR + col];
                ub[1] = Bc[(kb + t + 4) * BSTR + col];
                mma8(acc[0][nf], ua[0], ub);
                mma8(acc[1][nf], ua[1], ub);
                mma8(acc[2][nf], ua[2], ub);
                mma8(acc[3][nf], ua[3], ub);
            }
        }

        if (it < NT - 1) {
            unsigned* An = sg + ((it + 1) & 1) * GBUF;
            unsigned* Bn = An + ABUF;
#pragma unroll
            for (int i = 0; i < 8; i++) {
                *(uint4*)(An + (rowA + 16 * i) * ASTR + quadA * 4) =
                    make_uint4(f2t(ra[i].x), f2t(ra[i].y), f2t(ra[i].z), f2t(ra[i].w));
                *(uint4*)(Bn + (kB + 16 * (i >> 2)) * BSTR + (qB + 8 * (i & 3)) * 4) =
                    make_uint4(f2t(rb[i].x), f2t(rb[i].y), f2t(rb[i].z), f2t(rb[i].w));
            }
            __syncthreads();
        }
    }

    // epilogue
#pragma unroll
    for (int mf = 0; mf < 4; mf++) {
#pragma unroll
        for (int nf = 0; nf < 8; nf++) {
            int c = bn + wn * 64 + nf * 8 + 2 * t;
            float2 bi = *(const float2*)(bias + c);
#pragma unroll
            for (int half = 0; half < 2; half++) {
                int r = bm + wm * 64 + mf * 16 + g + half * 8;
                float v0 = acc[mf][nf][half * 2 + 0] + bi.x;
                float v1 = acc[mf][nf][half * 2 + 1] + bi.y;
                if (QKV) {
                    float2 lo = *(const float2*)(lora + (size_t)r * D3 + c);
                    v0 += lo.x; v1 += lo.y;
                    int which = c >> 10, rr = c & 1023;
                    int h = rr >> 6, d = rr & 63;
                    int b_ = r >> 11, s = r & 2047;
                    float* dst = (which == 0) ? g_q : (which == 1) ? g_k : g_v;
                    *(float2*)(dst + ((size_t)((b_ * NH + h) * SS + s)) * HD + d) =
                        make_float2(v0, v1);
                } else {
                    *(float2*)(C + (size_t)r * N + c) = make_float2(v0, v1);
                }
            }
        }
    }
}

// ---------------------------------------------------------------------------
// Flash attention, tf32 mma, causal. Block = (bh, 64-row q tile), 4 warps.
// Warp w owns rows w*16..w*16+15 (all 64 key cols / all 64 d cols).
// Smem: Ks[64][68], Vs[64][72], Ps[64][68] (Ps doubles as Q staging).
// __launch_bounds__(128,3): 3 CTAs/SM (12 warps) to hide latency.
// (unchanged from R5 — best known)
// ---------------------------------------------------------------------------
#define KSTR 68
#define VSTR 72
#define PSTR 68
#define FSMEM ((64*KSTR + 64*VSTR + 64*PSTR) * 4)   // 53248 bytes

__global__ __launch_bounds__(128, 3)
void flash_tf32()
{
    extern __shared__ unsigned smf[];
    unsigned* Ks = smf;
    unsigned* Vs = Ks + 64 * KSTR;
    unsigned* Ps = Vs + 64 * VSTR;

    const int qi = (int)gridDim.x - 1 - (int)blockIdx.x;   // heavy blocks first
    const int bh = blockIdx.y;
    const float* Qg = g_q + (size_t)bh * SS * HD;
    const float* Kg = g_k + (size_t)bh * SS * HD;
    const float* Vg = g_v + (size_t)bh * SS * HD;

    const int tid = threadIdx.x;
    const int warp = tid >> 5, lane = tid & 31;
    const int g = lane >> 2, t = lane & 3;
    const int rb = warp * 16;

    // stage Q (raw bits) into Ps area
#pragma unroll
    for (int i = 0; i < 8; i++) {
        int idx = tid + i * 128;
        int r = idx >> 4, d4 = (idx & 15) * 4;
        float4 q4 = *(const float4*)(Qg + (size_t)(qi * 64 + r) * HD + d4);
        *(uint4*)(Ps + r * PSTR + d4) =
            make_uint4(__float_as_uint(q4.x), __float_as_uint(q4.y),
                       __float_as_uint(q4.z), __float_as_uint(q4.w));
    }
    __syncthreads();

    // build Q fragments (scaled by 1/8, tf32)
    unsigned qa[8][4];
#pragma unroll
    for (int j8 = 0; j8 < 8; j8++) {
        qa[j8][0] = f2t(__uint_as_float(Ps[(rb + g) * PSTR + j8 * 8 + t]) * 0.125f);
        qa[j8][1] = f2t(__uint_as_float(Ps[(rb + g + 8) * PSTR + j8 * 8 + t]) * 0.125f);
        qa[j8][2] = f2t(__uint_as_float(Ps[(rb + g) * PSTR + j8 * 8 + t + 4]) * 0.125f);
        qa[j8][3] = f2t(__uint_as_float(Ps[(rb + g + 8) * PSTR + j8 * 8 + t + 4]) * 0.125f);
    }

    float o[8][4];
#pragma unroll
    for (int nf = 0; nf < 8; nf++)
#pragma unroll
        for (int e = 0; e < 4; e++) o[nf][e] = 0.f;
    float ml = -1e30f, mh = -1e30f, ll = 0.f, lh = 0.f;

    for (int j = 0; j <= qi; j++) {
        __syncthreads();   // prior iter done with Ks/Vs (and Q staging on iter 0)
        // load K,V tile (tf32-converted)
#pragma unroll
        for (int i = 0; i < 8; i++) {
            int idx = tid + i * 128;
            int r = idx >> 4, d4 = (idx & 15) * 4;
            float4 k4 = *(const float4*)(Kg + (size_t)(j * 64 + r) * HD + d4);
            *(uint4*)(Ks + r * KSTR + d4) =
                make_uint4(f2t(k4.x), f2t(k4.y), f2t(k4.z), f2t(k4.w));
            float4 v4 = *(const float4*)(Vg + (size_t)(j * 64 + r) * HD + d4);
            *(uint4*)(Vs + r * VSTR + d4) =
                make_uint4(f2t(v4.x), f2t(v4.y), f2t(v4.z), f2t(v4.w));
        }
        __syncthreads();

        // S = Q K^T  (rows rb..rb+15 x 64 keys)
        float s[8][4];
#pragma unroll
        for (int nf = 0; nf < 8; nf++) {
#pragma unroll
            for (int e = 0; e < 4; e++) s[nf][e] = 0.f;
#pragma unroll
            for (int j8 = 0; j8 < 8; j8++) {
                unsigned kb[2];
                kb[0] = Ks[(nf * 8 + g) * KSTR + j8 * 8 + t];
                kb[1] = Ks[(nf * 8 + g) * KSTR + j8 * 8 + t + 4];
                mma8(s[nf], qa[j8], kb);
            }
        }

        // causal mask on diagonal tile
        if (j == qi) {
#pragma unroll
            for (int nf = 0; nf < 8; nf++) {
                int c0 = nf * 8 + 2 * t, c1 = c0 + 1;
                int rlo = rb + g, rhi = rlo + 8;
                if (c0 > rlo) s[nf][0] = -1e30f;
                if (c1 > rlo) s[nf][1] = -1e30f;
                if (c0 > rhi) s[nf][2] = -1e30f;
                if (c1 > rhi) s[nf][3] = -1e30f;
            }
        }

        // online softmax (rows rlo = rb+g, rhi = rb+g+8)
        float mxl = -1e30f, mxh = -1e30f;
#pragma unroll
        for (int nf = 0; nf < 8; nf++) {
            mxl = fmaxf(mxl, fmaxf(s[nf][0], s[nf][1]));
            mxh = fmaxf(mxh, fmaxf(s[nf][2], s[nf][3]));
        }
        mxl = fmaxf(mxl, __shfl_xor_sync(0xffffffffu, mxl, 1));
        mxl = fmaxf(mxl, __shfl_xor_sync(0xffffffffu, mxl, 2));
        mxh = fmaxf(mxh, __shfl_xor_sync(0xffffffffu, mxh, 1));
        mxh = fmaxf(mxh, __shfl_xor_sync(0xffffffffu, mxh, 2));
        float nml = fmaxf(ml, mxl), nmh = fmaxf(mh, mxh);
        float cl = __expf(ml - nml), ch = __expf(mh - nmh);
        float suml = 0.f, sumh = 0.f;
#pragma unroll
        for (int nf = 0; nf < 8; nf++) {
            s[nf][0] = __expf(s[nf][0] - nml);
            s[nf][1] = __expf(s[nf][1] - nml);
            s[nf][2] = __expf(s[nf][2] - nmh);
            s[nf][3] = __expf(s[nf][3] - nmh);
            suml += s[nf][0] + s[nf][1];
            sumh += s[nf][2] + s[nf][3];
        }
        suml += __shfl_xor_sync(0xffffffffu, suml, 1);
        suml += __shfl_xor_sync(0xffffffffu, suml, 2);
        sumh += __shfl_xor_sync(0xffffffffu, sumh, 1);
        sumh += __shfl_xor_sync(0xffffffffu, sumh, 2);
        ll = ll * cl + suml; lh = lh * ch + sumh;
        ml = nml; mh = nmh;
#pragma unroll
        for (int nf = 0; nf < 8; nf++) {
            o[nf][0] *= cl; o[nf][1] *= cl;
            o[nf][2] *= ch; o[nf][3] *= ch;
        }

        // write P (tf32) to per-warp rows of Ps
#pragma unroll
        for (int nf = 0; nf < 8; nf++) {
            Ps[(rb + g) * PSTR + nf * 8 + 2 * t]     = f2t(s[nf][0]);
            Ps[(rb + g) * PSTR + nf * 8 + 2 * t + 1] = f2t(s[nf][1]);
            Ps[(rb + g + 8) * PSTR + nf * 8 + 2 * t]     = f2t(s[nf][2]);
            Ps[(rb + g + 8) * PSTR + nf * 8 + 2 * t + 1] = f2t(s[nf][3]);
        }
        __syncwarp();

        // O += P V
        unsigned pa[8][4];
#pragma unroll
        for (int j8 = 0; j8 < 8; j8++) {
            pa[j8][0] = Ps[(rb + g) * PSTR + j8 * 8 + t];
            pa[j8][1] = Ps[(rb + g + 8) * PSTR + j8 * 8 + t];
            pa[j8][2] = Ps[(rb + g) * PSTR + j8 * 8 + t + 4];
            pa[j8][3] = Ps[(rb + g + 8) * PSTR + j8 * 8 + t + 4];
        }
#pragma unroll
        for (int nf = 0; nf < 8; nf++) {
#pragma unroll
            for (int j8 = 0; j8 < 8; j8++) {
                unsigned vb[2];
                vb[0] = Vs[(j8 * 8 + t) * VSTR + nf * 8 + g];
                vb[1] = Vs[(j8 * 8 + t + 4) * VSTR + nf * 8 + g];
                mma8(o[nf], pa[j8], vb);
            }
        }
    }

    // normalize + store merged heads
    const int b_ = bh >> 4, h = bh & 15;
    float rl = 1.f / ll, rh = 1.f / lh;
    int rlo = qi * 64 + rb + g, rhi = rlo + 8;
#pragma unroll
    for (int nf = 0; nf < 8; nf++) {
        int d = nf * 8 + 2 * t;
        *(float2*)(g_attn + (size_t)(b_ * SS + rlo) * DD + h * HD + d) =
            make_float2(o[nf][0] * rl, o[nf][1] * rl);
        *(float2*)(g_attn + (size_t)(b_ * SS + rhi) * DD + h * HD + d) =
            make_float2(o[nf][2] * rh, o[nf][3] * rh);
    }
}

// ---------------------------------------------------------------------------
extern "C" void kernel_launch(void* const* d_in, const int* in_sizes, int n_in,
                              void* d_out, int out_size)
{
    const float* hs     = (const float*)d_in[0];
    const float* lora   = (const float*)d_in[1];
    const float* w_attn = (const float*)d_in[2];
    const float* b_attn = (const float*)d_in[3];
    const float* w_proj = (const float*)d_in[4];
    const float* b_proj = (const float*)d_in[5];
    float* out = (float*)d_out;

    cudaFuncSetAttribute(gemm_tf32<D3, true>,
                         cudaFuncAttributeMaxDynamicSharedMemorySize, GSMEM);
    cudaFuncSetAttribute(gemm_tf32<DD, false>,
                         cudaFuncAttributeMaxDynamicSharedMemorySize, GSMEM);
    cudaFuncSetAttribute(flash_tf32,
                         cudaFuncAttributeMaxDynamicSharedMemorySize, FSMEM);

    gemm_tf32<D3, true><<<dim3(D3 / 128, MTOT / 128), 128, GSMEM>>>(
        hs, w_attn, b_attn, lora, nullptr);
    flash_tf32<<<dim3(SS / 64, NB * NH), 128, FSMEM>>>();
    gemm_tf32<DD, false><<<dim3(DD / 128, MTOT / 128), 128, GSMEM>>>(
        nullptr, w_proj, b_proj, nullptr, out);
}

// round 7
// speedup vs baseline: 1.0406x; 1.0050x over previous
#include <cuda_runtime.h>
#include <math.h>

#define NB 2
#define SS 2048
#define NH 16
#define HD 64
#define DD 1024
#define D3 3072
#define MTOT (NB*SS)

// Scratch (allocation-free rule: device globals)
__device__ float g_q[NB*NH*SS*HD];     // [B,H,S,hd]
__device__ float g_k[NB*NH*SS*HD];
__device__ float g_v[NB*NH*SS*HD];
__device__ float g_attn[MTOT*DD];      // merged heads [B*S, D]

__device__ __forceinline__ unsigned f2t(float x) {
    unsigned u;
    asm("cvt.rna.tf32.f32 %0, %1;" : "=r"(u) : "f"(x));
    return u;
}

__device__ __forceinline__ void mma8(float* d, const unsigned* a, const unsigned* b) {
    asm volatile(
        "mma.sync.aligned.m16n8k8.row.col.f32.tf32.tf32.f32 "
        "{%0,%1,%2,%3}, {%4,%5,%6,%7}, {%8,%9}, {%0,%1,%2,%3};\n"
        : "+f"(d[0]), "+f"(d[1]), "+f"(d[2]), "+f"(d[3])
        : "r"(a[0]), "r"(a[1]), "r"(a[2]), "r"(a[3]), "r"(b[0]), "r"(b[1]));
}

// ---------------------------------------------------------------------------
// TF32 GEMM: C[M,N] = A[M,1024] @ W[1024,N] (+bias) (+lora, scatter q/k/v)
// 128x128 CTA tile, BK=32, 128 threads (4 warps as 2x2), warp tile 64x64.
// Fragment traffic: 1.0 LDS-word per MMA (vs 1.5 with 32x64 warp tiles).
// Double-buffered smem. As[m][k] stride 36, Bs[k][n] stride 136.
// __launch_bounds__(128,2): 2 CTAs/SM, reg budget 256/thread.
// ---------------------------------------------------------------------------
#define ASTR 36
#define BSTR 136
#define ABUF (128*ASTR)          // 4608 u32
#define BBUF (32*BSTR)           // 4352 u32
#define GBUF (ABUF + BBUF)       // per stage
#define GSMEM (2*GBUF*4)         // bytes = 71680

template<int N, bool QKV>
__global__ __launch_bounds__(128, 2)
void gemm_tf32(const float* __restrict__ Ain, const float* __restrict__ W,
               const float* __restrict__ bias, const float* __restrict__ lora,
               float* __restrict__ C)
{
    extern __shared__ unsigned sg[];
    const float* A = QKV ? Ain : g_attn;
    const int K = DD;

    const int tid  = threadIdx.x;
    const int warp = tid >> 5, lane = tid & 31;
    const int g = lane >> 2, t = lane & 3;
    const int wm = warp & 1, wn = warp >> 1;         // 2 x 2 warps
    const int bm = blockIdx.y * 128, bn = blockIdx.x * 128;

    // global/staging coords (8 float4 per thread per array)
    const int rowA = tid >> 3, quadA = tid & 7;      // A: rows rowA+16i, quad quadA
    const int kB = tid >> 3, qB = tid & 7;           // B: k rows kB+16(i>>2), quads qB+8(i&3)

    float acc[4][8][4];
#pragma unroll
    for (int mf = 0; mf < 4; mf++)
#pragma unroll
        for (int nf = 0; nf < 8; nf++)
#pragma unroll
            for (int e = 0; e < 4; e++) acc[mf][nf][e] = 0.f;

    float4 ra[8], rb[8];

    // prologue: tile 0
#pragma unroll
    for (int i = 0; i < 8; i++)
        ra[i] = *(const float4*)(A + (size_t)(bm + rowA + 16 * i) * K + quadA * 4);
#pragma unroll
    for (int i = 0; i < 8; i++)
        rb[i] = *(const float4*)(W + (size_t)(kB + 16 * (i >> 2)) * N + bn +
                                 (qB + 8 * (i & 3)) * 4);

    {
        unsigned* As = sg;
        unsigned* Bs = sg + ABUF;
#pragma unroll
        for (int i = 0; i < 8; i++) {
            *(uint4*)(As + (rowA + 16 * i) * ASTR + quadA * 4) =
                make_uint4(f2t(ra[i].x), f2t(ra[i].y), f2t(ra[i].z), f2t(ra[i].w));
            *(uint4*)(Bs + (kB + 16 * (i >> 2)) * BSTR + (qB + 8 * (i & 3)) * 4) =
                make_uint4(f2t(rb[i].x), f2t(rb[i].y), f2t(rb[i].z), f2t(rb[i].w));
        }
    }
    __syncthreads();

    const int NT = K / 32;   // 32 iterations
    for (int it = 0; it < NT; ++it) {
        if (it < NT - 1) {
            int k0 = (it + 1) * 32;
#pragma unroll
            for (int i = 0; i < 8; i++)
                ra[i] = *(const float4*)(A + (size_t)(bm + rowA + 16 * i) * K + k0 + quadA * 4);
#pragma unroll
            for (int i = 0; i < 8; i++)
                rb[i] = *(const float4*)(W + (size_t)(k0 + kB + 16 * (i >> 2)) * N + bn +
                                         (qB + 8 * (i & 3)) * 4);
        }

        const unsigned* Ac = sg + (it & 1) * GBUF;
        const unsigned* Bc = Ac + ABUF;
#pragma unroll
        for (int ks = 0; ks < 4; ks++) {
            const int kb = ks * 8;
            unsigned ua[4][4];
#pragma unroll
            for (int mf = 0; mf < 4; mf++) {
                int rbm = wm * 64 + mf * 16;
                ua[mf][0] = Ac[(rbm + g) * ASTR + kb + t];
                ua[mf][1] = Ac[(rbm + g + 8) * ASTR + kb + t];
                ua[mf][2] = Ac[(rbm + g) * ASTR + kb + t + 4];
                ua[mf][3] = Ac[(rbm + g + 8) * ASTR + kb + t + 4];
            }
#pragma unroll
            for (int nf = 0; nf < 8; nf++) {
                unsigned ub[2];
                int col = wn * 64 + nf * 8 + g;
                ub[0] = Bc[(kb + t) * BSTR + col];
                ub[1] = Bc[(kb + t + 4) * BSTR + col];
                mma8(acc[0][nf], ua[0], ub);
                mma8(acc[1][nf], ua[1], ub);
                mma8(acc[2][nf], ua[2], ub);
                mma8(acc[3][nf], ua[3], ub);
            }
        }

        if (it < NT - 1) {
            unsigned* An = sg + ((it + 1) & 1) * GBUF;
            unsigned* Bn = An + ABUF;
#pragma unroll
            for (int i = 0; i < 8; i++) {
                *(uint4*)(An + (rowA + 16 * i) * ASTR + quadA * 4) =
                    make_uint4(f2t(ra[i].x), f2t(ra[i].y), f2t(ra[i].z), f2t(ra[i].w));
                *(uint4*)(Bn + (kB + 16 * (i >> 2)) * BSTR + (qB + 8 * (i & 3)) * 4) =
                    make_uint4(f2t(rb[i].x), f2t(rb[i].y), f2t(rb[i].z), f2t(rb[i].w));
            }
            __syncthreads();
        }
    }

    // epilogue
#pragma unroll
    for (int mf = 0; mf < 4; mf++) {
#pragma unroll
        for (int nf = 0; nf < 8; nf++) {
            int c = bn + wn * 64 + nf * 8 + 2 * t;
            float2 bi = *(const float2*)(bias + c);
#pragma unroll
            for (int half = 0; half < 2; half++) {
                int r = bm + wm * 64 + mf * 16 + g + half * 8;
                float v0 = acc[mf][nf][half * 2 + 0] + bi.x;
                float v1 = acc[mf][nf][half * 2 + 1] + bi.y;
                if (QKV) {
                    float2 lo = *(const float2*)(lora + (size_t)r * D3 + c);
                    v0 += lo.x; v1 += lo.y;
                    int which = c >> 10, rr = c & 1023;
                    int h = rr >> 6, d = rr & 63;
                    int b_ = r >> 11, s = r & 2047;
                    float* dst = (which == 0) ? g_q : (which == 1) ? g_k : g_v;
                    *(float2*)(dst + ((size_t)((b_ * NH + h) * SS + s)) * HD + d) =
                        make_float2(v0, v1);
                } else {
                    *(float2*)(C + (size_t)r * N + c) = make_float2(v0, v1);
                }
            }
        }
    }
}

// ---------------------------------------------------------------------------
// Flash attention, tf32 mma, causal. Block = (bh, 64-row q tile), 4 warps.
// Warp w owns rows w*16..w*16+15 (all 64 key cols / all 64 d cols).
// Smem: Ks[64][68], Vs[64][72], Ps[64][68] (Ps doubles as Q staging).
// __launch_bounds__(128,3): 3 CTAs/SM (12 warps) to hide latency.
// (unchanged from R5 — best known)
// ---------------------------------------------------------------------------
#define KSTR 68
#define VSTR 72
#define PSTR 68
#define FSMEM ((64*KSTR + 64*VSTR + 64*PSTR) * 4)   // 53248 bytes

__global__ __launch_bounds__(128, 3)
void flash_tf32()
{
    extern __shared__ unsigned smf[];
    unsigned* Ks = smf;
    unsigned* Vs = Ks + 64 * KSTR;
    unsigned* Ps = Vs + 64 * VSTR;

    const int qi = (int)gridDim.x - 1 - (int)blockIdx.x;   // heavy blocks first
    const int bh = blockIdx.y;
    const float* Qg = g_q + (size_t)bh * SS * HD;
    const float* Kg = g_k + (size_t)bh * SS * HD;
    const float* Vg = g_v + (size_t)bh * SS * HD;

    const int tid = threadIdx.x;
    const int warp = tid >> 5, lane = tid & 31;
    const int g = lane >> 2, t = lane & 3;
    const int rb = warp * 16;

    // stage Q (raw bits) into Ps area
#pragma unroll
    for (int i = 0; i < 8; i++) {
        int idx = tid + i * 128;
        int r = idx >> 4, d4 = (idx & 15) * 4;
        float4 q4 = *(const float4*)(Qg + (size_t)(qi * 64 + r) * HD + d4);
        *(uint4*)(Ps + r * PSTR + d4) =
            make_uint4(__float_as_uint(q4.x), __float_as_uint(q4.y),
                       __float_as_uint(q4.z), __float_as_uint(q4.w));
    }
    __syncthreads();

    // build Q fragments (scaled by 1/8, tf32)
    unsigned qa[8][4];
#pragma unroll
    for (int j8 = 0; j8 < 8; j8++) {
        qa[j8][0] = f2t(__uint_as_float(Ps[(rb + g) * PSTR + j8 * 8 + t]) * 0.125f);
        qa[j8][1] = f2t(__uint_as_float(Ps[(rb + g + 8) * PSTR + j8 * 8 + t]) * 0.125f);
        qa[j8][2] = f2t(__uint_as_float(Ps[(rb + g) * PSTR + j8 * 8 + t + 4]) * 0.125f);
        qa[j8][3] = f2t(__uint_as_float(Ps[(rb + g + 8) * PSTR + j8 * 8 + t + 4]) * 0.125f);
    }

    float o[8][4];
#pragma unroll
    for (int nf = 0; nf < 8; nf++)
#pragma unroll
        for (int e = 0; e < 4; e++) o[nf][e] = 0.f;
    float ml = -1e30f, mh = -1e30f, ll = 0.f, lh = 0.f;

    for (int j = 0; j <= qi; j++) {
        __syncthreads();   // prior iter done with Ks/Vs (and Q staging on iter 0)
        // load K,V tile (tf32-converted)
#pragma unroll
        for (int i = 0; i < 8; i++) {
            int idx = tid + i * 128;
            int r = idx >> 4, d4 = (idx & 15) * 4;
            float4 k4 = *(const float4*)(Kg + (size_t)(j * 64 + r) * HD + d4);
            *(uint4*)(Ks + r * KSTR + d4) =
                make_uint4(f2t(k4.x), f2t(k4.y), f2t(k4.z), f2t(k4.w));
            float4 v4 = *(const float4*)(Vg + (size_t)(j * 64 + r) * HD + d4);
            *(uint4*)(Vs + r * VSTR + d4) =
                make_uint4(f2t(v4.x), f2t(v4.y), f2t(v4.z), f2t(v4.w));
        }
        __syncthreads();

        // S = Q K^T  (rows rb..rb+15 x 64 keys)
        float s[8][4];
#pragma unroll
        for (int nf = 0; nf < 8; nf++) {
#pragma unroll
            for (int e = 0; e < 4; e++) s[nf][e] = 0.f;
#pragma unroll
            for (int j8 = 0; j8 < 8; j8++) {
                unsigned kb[2];
                kb[0] = Ks[(nf * 8 + g) * KSTR + j8 * 8 + t];
                kb[1] = Ks[(nf * 8 + g) * KSTR + j8 * 8 + t + 4];
                mma8(s[nf], qa[j8], kb);
            }
        }

        // causal mask on diagonal tile
        if (j == qi) {
#pragma unroll
            for (int nf = 0; nf < 8; nf++) {
                int c0 = nf * 8 + 2 * t, c1 = c0 + 1;
                int rlo = rb + g, rhi = rlo + 8;
                if (c0 > rlo) s[nf][0] = -1e30f;
                if (c1 > rlo) s[nf][1] = -1e30f;
                if (c0 > rhi) s[nf][2] = -1e30f;
                if (c1 > rhi) s[nf][3] = -1e30f;
            }
        }

        // online softmax (rows rlo = rb+g, rhi = rb+g+8)
        float mxl = -1e30f, mxh = -1e30f;
#pragma unroll
        for (int nf = 0; nf < 8; nf++) {
            mxl = fmaxf(mxl, fmaxf(s[nf][0], s[nf][1]));
            mxh = fmaxf(mxh, fmaxf(s[nf][2], s[nf][3]));
        }
        mxl = fmaxf(mxl, __shfl_xor_sync(0xffffffffu, mxl, 1));
        mxl = fmaxf(mxl, __shfl_xor_sync(0xffffffffu, mxl, 2));
        mxh = fmaxf(mxh, __shfl_xor_sync(0xffffffffu, mxh, 1));
        mxh = fmaxf(mxh, __shfl_xor_sync(0xffffffffu, mxh, 2));
        float nml = fmaxf(ml, mxl), nmh = fmaxf(mh, mxh);
        float cl = __expf(ml - nml), ch = __expf(mh - nmh);
        float suml = 0.f, sumh = 0.f;
#pragma unroll
        for (int nf = 0; nf < 8; nf++) {
            s[nf][0] = __expf(s[nf][0] - nml);
            s[nf][1] = __expf(s[nf][1] - nml);
            s[nf][2] = __expf(s[nf][2] - nmh);
            s[nf][3] = __expf(s[nf][3] - nmh);
            suml += s[nf][0] + s[nf][1];
            sumh += s[nf][2] + s[nf][3];
        }
        suml += __shfl_xor_sync(0xffffffffu, suml, 1);
        suml += __shfl_xor_sync(0xffffffffu, suml, 2);
        sumh += __shfl_xor_sync(0xffffffffu, sumh, 1);
        sumh += __shfl_xor_sync(0xffffffffu, sumh, 2);
        ll = ll * cl + suml; lh = lh * ch + sumh;
        ml = nml; mh = nmh;
#pragma unroll
        for (int nf = 0; nf < 8; nf++) {
            o[nf][0] *= cl; o[nf][1] *= cl;
            o[nf][2] *= ch; o[nf][3] *= ch;
        }

        // write P (tf32) to per-warp rows of Ps
#pragma unroll
        for (int nf = 0; nf < 8; nf++) {
            Ps[(rb + g) * PSTR + nf * 8 + 2 * t]     = f2t(s[nf][0]);
            Ps[(rb + g) * PSTR + nf * 8 + 2 * t + 1] = f2t(s[nf][1]);
            Ps[(rb + g + 8) * PSTR + nf * 8 + 2 * t]     = f2t(s[nf][2]);
            Ps[(rb + g + 8) * PSTR + nf * 8 + 2 * t + 1] = f2t(s[nf][3]);
        }
        __syncwarp();

        // O += P V
        unsigned pa[8][4];
#pragma unroll
        for (int j8 = 0; j8 < 8; j8++) {
            pa[j8][0] = Ps[(rb + g) * PSTR + j8 * 8 + t];
            pa[j8][1] = Ps[(rb + g + 8) * PSTR + j8 * 8 + t];
            pa[j8][2] = Ps[(rb + g) * PSTR + j8 * 8 + t + 4];
            pa[j8][3] = Ps[(rb + g + 8) * PSTR + j8 * 8 + t + 4];
        }
#pragma unroll
        for (int nf = 0; nf < 8; nf++) {
#pragma unroll
            for (int j8 = 0; j8 < 8; j8++) {
                unsigned vb[2];
                vb[0] = Vs[(j8 * 8 + t) * VSTR + nf * 8 + g];
                vb[1] = Vs[(j8 * 8 + t + 4) * VSTR + nf * 8 + g];
                mma8(o[nf], pa[j8], vb);
            }
        }
    }

    // normalize + store merged heads
    const int b_ = bh >> 4, h = bh & 15;
    float rl = 1.f / ll, rh = 1.f / lh;
    int rlo = qi * 64 + rb + g, rhi = rlo + 8;
#pragma unroll
    for (int nf = 0; nf < 8; nf++) {
        int d = nf * 8 + 2 * t;
        *(float2*)(g_attn + (size_t)(b_ * SS + rlo) * DD + h * HD + d) =
            make_float2(o[nf][0] * rl, o[nf][1] * rl);
        *(float2*)(g_attn + (size_t)(b_ * SS + rhi) * DD + h * HD + d) =
            make_float2(o[nf][2] * rh, o[nf][3] * rh);
    }
}

// ---------------------------------------------------------------------------
extern "C" void kernel_launch(void* const* d_in, const int* in_sizes, int n_in,
                              void* d_out, int out_size)
{
    const float* hs     = (const float*)d_in[0];
    const float* lora   = (const float*)d_in[1];
    const float* w_attn = (const float*)d_in[2];
    const float* b_attn = (const float*)d_in[3];
    const float* w_proj = (const float*)d_in[4];
    const float* b_proj = (const float*)d_in[5];
    float* out = (float*)d_out;

    cudaFuncSetAttribute(gemm_tf32<D3, true>,
                         cudaFuncAttributeMaxDynamicSharedMemorySize, GSMEM);
    cudaFuncSetAttribute(gemm_tf32<DD, false>,
                         cudaFuncAttributeMaxDynamicSharedMemorySize, GSMEM);
    cudaFuncSetAttribute(flash_tf32,
                         cudaFuncAttributeMaxDynamicSharedMemorySize, FSMEM);

    gemm_tf32<D3, true><<<dim3(D3 / 128, MTOT / 128), 128, GSMEM>>>(
        hs, w_attn, b_attn, lora, nullptr);
    flash_tf32<<<dim3(SS / 64, NB * NH), 128, FSMEM>>>();
    gemm_tf32<DD, false><<<dim3(DD / 128, MTOT / 128), 128, GSMEM>>>(
        nullptr, w_proj, b_proj, nullptr, out);
}